// round 13
// baseline (speedup 1.0000x reference)
#include <cuda_runtime.h>
#include <cuda_fp16.h>
#include <mma.h>

using namespace nvcuda;

#define N_NODES 50000
#define N_EDGES 800000
#define HDIM    128
#define NPAD    50048           // ceil(N/128)*128
#define WSZ     (HDIM * HDIM)
#define SCAN_BLOCKS 98          // 98 * 512 = 50176 >= N_NODES

// ---------------- scratch (device globals; no allocation allowed) ----------
__device__ float  g_xd   [NPAD * HDIM];              // x @ We0 + be (fp32)
__device__ __half g_xsh  [NPAD * HDIM];              // half(x @ We1)
__device__ __half g_aggh [NPAD * HDIM];              // half(segment_sum)
__device__ __half g_hWh  [NPAD * HDIM];              // half(agg @ Wc + bgwo)
__device__ __half g_eawh [(size_t)N_EDGES * HDIM];   // half(ea@We2 + xs[src]), CSR order
__device__ __half g_Weh  [3 * WSZ];
__device__ __half g_Wch  [WSZ];                      // half(Wg@Wo)
__device__ float  g_bgwo [HDIM];                     // bg@Wo
// CSR machinery (deg arrays are zero at every kernel_launch entry: statically
// zero-initialized on load, and re-zeroed by k_scatteridx at the end of each run)
__device__ int  g_deg_in [N_NODES];
__device__ int  g_deg_out[N_NODES];
__device__ int  g_off_in [N_NODES + 1];
__device__ int  g_off_out[N_NODES + 1];
__device__ int  g_cur_in [N_NODES];
__device__ int  g_cur_out[N_NODES];
__device__ int  g_bsum   [2 * SCAN_BLOCKS];
__device__ int  g_pos2   [N_EDGES];     // edge id -> in-CSR position
__device__ int  g_csr_out_dst[N_EDGES]; // out-CSR: dest node per out-edge

// ---------------- small utility kernels ------------------------------------
__global__ void k_hist(const int* __restrict__ ei, int* __restrict__ din, int* __restrict__ dout) {
    int e = blockIdx.x * 256 + threadIdx.x;
    if (e >= N_EDGES) return;
    atomicAdd(&dout[ei[e]], 1);            // src
    atomicAdd(&din[ei[N_EDGES + e]], 1);   // dst
}

// Phase A: per-block (512-elem) degree sums. grid = 2*SCAN_BLOCKS.
__global__ void k_blocksum(const int* __restrict__ din, const int* __restrict__ dout,
                           int* __restrict__ bsum) {
    const int* deg = (blockIdx.x < SCAN_BLOCKS) ? din : dout;
    const int b = (blockIdx.x < SCAN_BLOCKS) ? blockIdx.x : blockIdx.x - SCAN_BLOCKS;
    const int i = b * 512 + threadIdx.x;
    int v = (i < N_NODES) ? deg[i] : 0;

    __shared__ int ws[16];
    const int lane = threadIdx.x & 31, w = threadIdx.x >> 5;
#pragma unroll
    for (int o = 16; o; o >>= 1) v += __shfl_down_sync(0xffffffffu, v, o);
    if (lane == 0) ws[w] = v;
    __syncthreads();
    if (threadIdx.x < 16) {
        int t = ws[threadIdx.x];
#pragma unroll
        for (int o = 8; o; o >>= 1) t += __shfl_down_sync(0xffffu, t, o);
        if (threadIdx.x == 0) bsum[blockIdx.x] = t;
    }
}

// Phase B: exclusive scan of each 98-entry segment. grid = 2, block = 128.
__global__ void k_bscan(int* __restrict__ bsum, int* __restrict__ oin, int* __restrict__ oout) {
    __shared__ int sp[128];
    const int base = blockIdx.x * SCAN_BLOCKS;
    const int t = threadIdx.x;
    int v = (t < SCAN_BLOCKS) ? bsum[base + t] : 0;
    sp[t] = v;
    __syncthreads();
#pragma unroll
    for (int d = 1; d < 128; d <<= 1) {
        int u = (t >= d) ? sp[t - d] : 0;
        __syncthreads();
        sp[t] += u;
        __syncthreads();
    }
    if (t < SCAN_BLOCKS) bsum[base + t] = sp[t] - v;   // exclusive
    if (t == 0) (blockIdx.x ? oout : oin)[N_NODES] = N_EDGES;
}

// Phase C: per-block exclusive scan + block offset -> off/cur. grid = 2*SCAN_BLOCKS.
__global__ void k_scatteroff(const int* __restrict__ din, const int* __restrict__ dout,
                             const int* __restrict__ bsum,
                             int* __restrict__ oin, int* __restrict__ cin,
                             int* __restrict__ oout, int* __restrict__ cout_) {
    const bool isout = blockIdx.x >= SCAN_BLOCKS;
    const int* deg = isout ? dout : din;
    int* off = isout ? oout : oin;
    int* cur = isout ? cout_ : cin;
    const int b = isout ? blockIdx.x - SCAN_BLOCKS : blockIdx.x;
    const int i = b * 512 + threadIdx.x;
    int v = (i < N_NODES) ? deg[i] : 0;

    const int lane = threadIdx.x & 31, w = threadIdx.x >> 5;
    int incl = v;
#pragma unroll
    for (int o = 1; o < 32; o <<= 1) {
        int u = __shfl_up_sync(0xffffffffu, incl, o);
        if (lane >= o) incl += u;
    }
    __shared__ int ws[16], wo[16];
    if (lane == 31) ws[w] = incl;
    __syncthreads();
    if (threadIdx.x < 16) {
        int t = ws[threadIdx.x];
        int ti = t;
#pragma unroll
        for (int o = 1; o < 16; o <<= 1) {
            int u = __shfl_up_sync(0xffffu, ti, o);
            if (threadIdx.x >= o) ti += u;
        }
        wo[threadIdx.x] = ti - t;                      // exclusive warp offset
    }
    __syncthreads();
    int excl = incl - v + wo[w] + bsum[blockIdx.x];
    if (i < N_NODES) { off[i] = excl; cur[i] = excl; }
}

// Runs AFTER all readers of din/dout: also re-zeroes them for the next replay.
__global__ void k_scatteridx(const int* __restrict__ ei,
                             int* __restrict__ cin, int* __restrict__ cout_,
                             int* __restrict__ pos2, int* __restrict__ odst,
                             int* __restrict__ din, int* __restrict__ dout) {
    int e = blockIdx.x * 256 + threadIdx.x;
    if (e >= N_EDGES) return;
    if (e < N_NODES) { din[e] = 0; dout[e] = 0; }      // reset for next replay
    int s = ei[e];
    int d = ei[N_EDGES + e];
    int p1 = atomicAdd(&cin[d], 1);
    pos2[e] = p1;                          // eid -> csr position (sequential write)
    int p2 = atomicAdd(&cout_[s], 1);
    odst[p2] = d;
}

__global__ void k_f2h(const float* __restrict__ s, __half* __restrict__ d, int n) {
    int i = blockIdx.x * blockDim.x + threadIdx.x;
    if (i < n) d[i] = __float2half(s[i]);
}

// Wc = Wg @ Wo  (fp32 accumulate, round once to half)
__global__ void k_wc(const float* __restrict__ Wg, const float* __restrict__ Wo,
                     __half* __restrict__ Wch) {
    int i = blockIdx.x * blockDim.x + threadIdx.x;
    int r = i >> 7, c = i & 127;
    float s = 0.f;
#pragma unroll 8
    for (int k = 0; k < 128; k++) s += Wg[r * 128 + k] * Wo[k * 128 + c];
    Wch[i] = __float2half(s);
}

__global__ void k_bgwo(const float* __restrict__ bg, const float* __restrict__ Wo,
                       float* __restrict__ bgwo) {
    int c = threadIdx.x;
    float s = 0.f;
#pragma unroll 8
    for (int k = 0; k < 128; k++) s += bg[k] * Wo[k * 128 + c];
    bgwo[c] = s;
}

__device__ __forceinline__ float4 ldh4(const __half* p) {   // 4 halves via one 8B LDG
    uint2 u = *reinterpret_cast<const uint2*>(p);
    __half2 h0 = *reinterpret_cast<__half2*>(&u.x);
    __half2 h1 = *reinterpret_cast<__half2*>(&u.y);
    float2 f0 = __half22float2(h0);
    float2 f1 = __half22float2(h1);
    return make_float4(f0.x, f0.y, f1.x, f1.y);
}

// ---------------- unified [M,128]@[128,128] GEMM ----------------------------
template <bool A_FP32, bool HALF_OUT>
__global__ void __launch_bounds__(256, 3)
k_mm(const void* __restrict__ Av, const __half* __restrict__ B,
     const float* __restrict__ bias, void* __restrict__ C, int m_rows) {
    extern __shared__ char smem[];
    __half* sA = reinterpret_cast<__half*>(smem);            // 128 x 136 halves
    __half* sB = reinterpret_cast<__half*>(smem + 34816);    // 128 x 136 halves
    float*  sT = reinterpret_cast<float*>(smem);             // reused staging

    const int tid  = threadIdx.x;
    const int warp = tid >> 5;
    const int lane = tid & 31;
    const size_t r0 = (size_t)blockIdx.x * 128;

    if (A_FP32) {
        const float* A = (const float*)Av;
#pragma unroll
        for (int j = 0; j < 16; j++) {
            int idx = j * 256 + tid;
            int row = idx >> 5, c4 = idx & 31;
            float4 v = make_float4(0.f, 0.f, 0.f, 0.f);
            if ((int)(r0 + row) < m_rows)
                v = *reinterpret_cast<const float4*>(A + (r0 + row) * 128 + c4 * 4);
            *reinterpret_cast<__half2*>(sA + row * 136 + c4 * 4)     = __floats2half2_rn(v.x, v.y);
            *reinterpret_cast<__half2*>(sA + row * 136 + c4 * 4 + 2) = __floats2half2_rn(v.z, v.w);
        }
    } else {
        const __half* A = (const __half*)Av;
#pragma unroll
        for (int j = 0; j < 32; j++) {
            int idx = j * 256 + tid;
            int row = idx >> 6, c2 = idx & 63;
            __half2 v = __floats2half2_rn(0.f, 0.f);
            if ((int)(r0 + row) < m_rows)
                v = *reinterpret_cast<const __half2*>(A + (r0 + row) * 128 + c2 * 2);
            *reinterpret_cast<__half2*>(sA + row * 136 + c2 * 2) = v;
        }
    }
#pragma unroll
    for (int j = 0; j < 32; j++) {                   // stage B
        int idx = j * 256 + tid;
        int row = idx >> 6, c2 = idx & 63;
        *reinterpret_cast<__half2*>(sB + row * 136 + c2 * 2) =
            *reinterpret_cast<const __half2*>(B + row * 128 + c2 * 2);
    }
    __syncthreads();

    wmma::fragment<wmma::accumulator, 16, 16, 16, float> acc[8];
#pragma unroll
    for (int n = 0; n < 8; n++) wmma::fill_fragment(acc[n], 0.f);

#pragma unroll
    for (int k = 0; k < 8; k++) {
        wmma::fragment<wmma::matrix_a, 16, 16, 16, __half, wmma::row_major> a;
        wmma::load_matrix_sync(a, sA + warp * 16 * 136 + k * 16, 136);
#pragma unroll
        for (int n = 0; n < 8; n++) {
            wmma::fragment<wmma::matrix_b, 16, 16, 16, __half, wmma::row_major> b;
            wmma::load_matrix_sync(b, sB + (k * 16) * 136 + n * 16, 136);
            wmma::mma_sync(acc[n], a, b, acc[n]);
        }
    }
    __syncthreads();                                 // done with sA/sB

    float* my = sT + warp * 16 * 132;
#pragma unroll
    for (int n = 0; n < 8; n++)
        wmma::store_matrix_sync(my + n * 16, acc[n], 132, wmma::mem_row_major);
    __syncwarp();                                    // each warp reads its own rows

    float4 bv = make_float4(0.f, 0.f, 0.f, 0.f);
    if (bias) bv = *reinterpret_cast<const float4*>(bias + lane * 4);

    const size_t row0 = r0 + warp * 16;
#pragma unroll
    for (int r = 0; r < 16; r++) {
        float4 v = *reinterpret_cast<const float4*>(my + r * 132 + lane * 4);
        v.x += bv.x; v.y += bv.y; v.z += bv.z; v.w += bv.w;
        if (HALF_OUT) {
            __half2 h0 = __floats2half2_rn(v.x, v.y);
            __half2 h1 = __floats2half2_rn(v.z, v.w);
            uint2 u = make_uint2(*(unsigned*)&h0, *(unsigned*)&h1);
            *reinterpret_cast<uint2*>((__half*)C + (row0 + r) * 128 + lane * 4) = u;
        } else {
            *reinterpret_cast<float4*>((float*)C + (row0 + r) * 128 + lane * 4) = v;
        }
    }
}

// ------- edge GEMM + xs fold + CSR scatter-write ----------------------------
// eawh[pos2[e]] = half( ea[e]@We2 + xs[src[e]] )
__global__ void __launch_bounds__(256, 3)
k_eaw(const float* __restrict__ ea, const int* __restrict__ ei,
      const __half* __restrict__ xsh, const int* __restrict__ pos2,
      const __half* __restrict__ W2, __half* __restrict__ eaw) {
    extern __shared__ char smem[];
    __half* sA   = reinterpret_cast<__half*>(smem);            // 128 x 136
    __half* sB   = reinterpret_cast<__half*>(smem + 34816);    // 128 x 136
    int*    sSrc = reinterpret_cast<int*>(smem + 69632);       // 128
    int*    sPos = reinterpret_cast<int*>(smem + 70144);       // 128
    float*  sT   = reinterpret_cast<float*>(smem);             // per-warp strips

    const int tid  = threadIdx.x;
    const int warp = tid >> 5;
    const int lane = tid & 31;
    const size_t e0 = (size_t)blockIdx.x * 128;

    if (tid < 128) {
        sSrc[tid] = ei[e0 + tid];                    // src = edge_index[0]
        sPos[tid] = pos2[e0 + tid];
    }
#pragma unroll
    for (int j = 0; j < 16; j++) {                   // stream A tile (sequential DRAM)
        int idx = j * 256 + tid;
        int row = idx >> 5, c4 = idx & 31;
        float4 v = *reinterpret_cast<const float4*>(ea + (e0 + row) * 128 + c4 * 4);
        *reinterpret_cast<__half2*>(sA + row * 136 + c4 * 4)     = __floats2half2_rn(v.x, v.y);
        *reinterpret_cast<__half2*>(sA + row * 136 + c4 * 4 + 2) = __floats2half2_rn(v.z, v.w);
    }
#pragma unroll
    for (int j = 0; j < 32; j++) {                   // stage W2 (L2-resident)
        int idx = j * 256 + tid;
        int row = idx >> 6, c2 = idx & 63;
        *reinterpret_cast<__half2*>(sB + row * 136 + c2 * 2) =
            *reinterpret_cast<const __half2*>(W2 + row * 128 + c2 * 2);
    }
    __syncthreads();

    wmma::fragment<wmma::accumulator, 16, 16, 16, float> acc[8];
#pragma unroll
    for (int n = 0; n < 8; n++) wmma::fill_fragment(acc[n], 0.f);

#pragma unroll
    for (int k = 0; k < 8; k++) {
        wmma::fragment<wmma::matrix_a, 16, 16, 16, __half, wmma::row_major> a;
        wmma::load_matrix_sync(a, sA + warp * 16 * 136 + k * 16, 136);
#pragma unroll
        for (int n = 0; n < 8; n++) {
            wmma::fragment<wmma::matrix_b, 16, 16, 16, __half, wmma::row_major> b;
            wmma::load_matrix_sync(b, sB + (k * 16) * 136 + n * 16, 136);
            wmma::mma_sync(acc[n], a, b, acc[n]);
        }
    }
    __syncthreads();                                 // all warps done reading sA/sB

    // warp-local epilogue: xs gathered here (L2-resident table)
    float* my = sT + warp * (16 * 132);
#pragma unroll
    for (int n = 0; n < 8; n++)
        wmma::store_matrix_sync(my + n * 16, acc[n], 132, wmma::mem_row_major);
    __syncwarp();

#pragma unroll
    for (int r = 0; r < 16; r++) {
        int row = warp * 16 + r;
        float4 t = *reinterpret_cast<const float4*>(my + r * 132 + lane * 4);
        float4 v = ldh4(xsh + (size_t)sSrc[row] * 128 + lane * 4);
        __half2 h0 = __floats2half2_rn(t.x + v.x, t.y + v.y);
        __half2 h1 = __floats2half2_rn(t.z + v.z, t.w + v.w);
        uint2 u = make_uint2(*(unsigned*)&h0, *(unsigned*)&h1);
        *reinterpret_cast<uint2*>(eaw + (size_t)sPos[row] * 128 + lane * 4) = u;
    }
}

// ------- aggregation: aggh[n] = half( sum silu(xd[n] + eawh[i]) ), sequential
__device__ __forceinline__ float silu1(float v) { return v / (1.f + __expf(-v)); }

__global__ void k_agg(const int* __restrict__ off,
                      const float* __restrict__ xd, const __half* __restrict__ eaw,
                      __half* __restrict__ aggh) {
    const int w    = (blockIdx.x * 256 + threadIdx.x) >> 5;    // node id
    const int lane = threadIdx.x & 31;
    if (w >= N_NODES) return;

    float4 base = *reinterpret_cast<const float4*>(xd + (size_t)w * 128 + lane * 4);

    float4 acc = make_float4(0.f, 0.f, 0.f, 0.f);
    const int beg = off[w], end = off[w + 1];
#pragma unroll 4
    for (int i = beg; i < end; i++) {                // sequential eaw stream
        float4 t = ldh4(eaw + (size_t)i * 128 + lane * 4);
        acc.x += silu1(base.x + t.x);
        acc.y += silu1(base.y + t.y);
        acc.z += silu1(base.z + t.z);
        acc.w += silu1(base.w + t.w);
    }
    __half2 h0 = __floats2half2_rn(acc.x, acc.y);
    __half2 h1 = __floats2half2_rn(acc.z, acc.w);
    uint2 u = make_uint2(*(unsigned*)&h0, *(unsigned*)&h1);
    *reinterpret_cast<uint2*>(aggh + (size_t)w * 128 + lane * 4) = u;
}

// ---------------- output: out[n] = bo + sum_out hW[dst] ---------------------
__global__ void k_out(const int* __restrict__ off, const int* __restrict__ odst,
                      const __half* __restrict__ hWh, const float* __restrict__ bo,
                      float* __restrict__ out) {
    const int w    = (blockIdx.x * 256 + threadIdx.x) >> 5;
    const int lane = threadIdx.x & 31;
    if (w >= N_NODES) return;

    float4 acc = *reinterpret_cast<const float4*>(bo + lane * 4);
    const int beg = off[w], end = off[w + 1];
#pragma unroll 4
    for (int i = beg; i < end; i++) {
        int d = odst[i];
        float4 v = ldh4(hWh + (size_t)d * 128 + lane * 4);
        acc.x += v.x; acc.y += v.y; acc.z += v.z; acc.w += v.w;
    }
    *reinterpret_cast<float4*>(out + (size_t)w * 128 + lane * 4) = acc;
}

// ---------------- launch ----------------------------------------------------
extern "C" void kernel_launch(void* const* d_in, const int* in_sizes, int n_in,
                              void* d_out, int out_size) {
    const float* x  = (const float*)d_in[0];
    const int*   ei = (const int*)d_in[1];     // int32 (JAX x64 disabled)
    const float* ea = (const float*)d_in[2];
    const float* We = (const float*)d_in[3];
    const float* be = (const float*)d_in[4];
    const float* Wg = (const float*)d_in[5];
    const float* bg = (const float*)d_in[6];
    // d_in[7]=Wa, d_in[8]=ba: dead (softmax over size-1 axis == 1)
    const float* Wo = (const float*)d_in[9];
    const float* bo = (const float*)d_in[10];
    float*       out = (float*)d_out;

    void *p;
    __half *xsh, *aggh, *hWh, *eawh, *Weh, *Wch;
    float *xd, *bgwo;
    int *din, *dout_, *oin, *oout, *cin, *cout_, *bsum, *pos2, *odst;
    cudaGetSymbolAddress(&p, g_xd);          xd    = (float*)p;
    cudaGetSymbolAddress(&p, g_xsh);         xsh   = (__half*)p;
    cudaGetSymbolAddress(&p, g_aggh);        aggh  = (__half*)p;
    cudaGetSymbolAddress(&p, g_hWh);         hWh   = (__half*)p;
    cudaGetSymbolAddress(&p, g_eawh);        eawh  = (__half*)p;
    cudaGetSymbolAddress(&p, g_Weh);         Weh   = (__half*)p;
    cudaGetSymbolAddress(&p, g_Wch);         Wch   = (__half*)p;
    cudaGetSymbolAddress(&p, g_bgwo);        bgwo  = (float*)p;
    cudaGetSymbolAddress(&p, g_deg_in);      din   = (int*)p;
    cudaGetSymbolAddress(&p, g_deg_out);     dout_ = (int*)p;
    cudaGetSymbolAddress(&p, g_off_in);      oin   = (int*)p;
    cudaGetSymbolAddress(&p, g_off_out);     oout  = (int*)p;
    cudaGetSymbolAddress(&p, g_cur_in);      cin   = (int*)p;
    cudaGetSymbolAddress(&p, g_cur_out);     cout_ = (int*)p;
    cudaGetSymbolAddress(&p, g_bsum);        bsum  = (int*)p;
    cudaGetSymbolAddress(&p, g_pos2);        pos2  = (int*)p;
    cudaGetSymbolAddress(&p, g_csr_out_dst); odst  = (int*)p;

    const size_t mm_shmem  = 69632;           // sA + sB
    const size_t eaw_shmem = 70656;           // sA + sB + sSrc + sPos
    cudaFuncSetAttribute(k_mm<true,  false>, cudaFuncAttributeMaxDynamicSharedMemorySize, (int)mm_shmem);
    cudaFuncSetAttribute(k_mm<true,  true >, cudaFuncAttributeMaxDynamicSharedMemorySize, (int)mm_shmem);
    cudaFuncSetAttribute(k_mm<false, true >, cudaFuncAttributeMaxDynamicSharedMemorySize, (int)mm_shmem);
    cudaFuncSetAttribute(k_eaw,              cudaFuncAttributeMaxDynamicSharedMemorySize, (int)eaw_shmem);

    const int gblocks = NPAD / 128;           // 391
    const int eblocks = N_EDGES / 128;        // 6250
    const int nwarp_blocks = (N_NODES * 32 + 255) / 256;   // 6250

    // deg arrays enter zeroed (static init on first call; k_scatteridx re-zeroes
    // them each run for the next replay)
    k_f2h<<<(3 * WSZ + 255) / 256, 256>>>(We, Weh, 3 * WSZ);
    k_hist<<<(N_EDGES + 255) / 256, 256>>>(ei, din, dout_);
    k_mm<true, true ><<<gblocks, 256, mm_shmem>>>(x, Weh + WSZ, nullptr, xsh, N_NODES);

    // hierarchical CSR offset scan
    k_blocksum<<<2 * SCAN_BLOCKS, 512>>>(din, dout_, bsum);
    k_bscan<<<2, 128>>>(bsum, oin, oout);
    k_scatteroff<<<2 * SCAN_BLOCKS, 512>>>(din, dout_, bsum, oin, cin, oout, cout_);

    k_scatteridx<<<(N_EDGES + 255) / 256, 256>>>(ei, cin, cout_, pos2, odst, din, dout_);

    // edge GEMM + xs fold, scatter-written into in-CSR order
    k_eaw<<<eblocks, 256, eaw_shmem>>>(ea, ei, xsh, pos2, Weh + 2 * WSZ, eawh);

    k_wc<<<64, 256>>>(Wg, Wo, Wch);
    k_bgwo<<<1, 128>>>(bg, Wo, bgwo);
    k_mm<true, false><<<gblocks, 256, mm_shmem>>>(x, Weh, be, xd, N_NODES);   // be folded

    // fully sequential aggregation
    k_agg<<<nwarp_blocks, 256>>>(oin, xd, eawh, aggh);

    // hW = agg @ (Wg@Wo) + bg@Wo
    k_mm<false, true><<<gblocks, 256, mm_shmem>>>(aggh, Wch, bgwo, hWh, NPAD);

    // out[n] = bo + sum hW[dst] over out-edges
    k_out<<<nwarp_blocks, 256>>>(oout, odst, hWh, bo, out);
}

// round 14
// speedup vs baseline: 1.0906x; 1.0906x over previous
#include <cuda_runtime.h>
#include <cuda_fp16.h>
#include <mma.h>

using namespace nvcuda;

#define N_NODES 50000
#define N_EDGES 800000
#define HDIM    128
#define NPAD    50048           // ceil(N/128)*128
#define WSZ     (HDIM * HDIM)
#define SCAN_BLOCKS 98          // 98 * 512 = 50176 >= N_NODES

// ---------------- scratch (device globals; no allocation allowed) ----------
__device__ float  g_xd   [NPAD * HDIM];              // x @ We0 + be (fp32)
__device__ __half g_xsh  [NPAD * HDIM];              // half(x @ We1)
__device__ __half g_aggh [NPAD * HDIM];              // half(segment_sum)
__device__ __half g_hWh  [NPAD * HDIM];              // half(agg @ Wc + bgwo)
__device__ __half g_eawh [(size_t)N_EDGES * HDIM];   // half(ea@We2 + xs[src]), CSR order
__device__ __half g_Weh  [3 * WSZ];
__device__ __half g_Wch  [WSZ];                      // half(Wg@Wo)
__device__ float  g_bgwo [HDIM];                     // bg@Wo
// CSR machinery (deg arrays are zero at every kernel_launch entry: statically
// zero-initialized on load, and re-zeroed by k_scatteridx at the end of each run)
__device__ int  g_deg_in [N_NODES];
__device__ int  g_deg_out[N_NODES];
__device__ int  g_off_in [N_NODES + 1];
__device__ int  g_off_out[N_NODES + 1];
__device__ int  g_cur_in [N_NODES];
__device__ int  g_cur_out[N_NODES];
__device__ int  g_bsum   [2 * SCAN_BLOCKS];
__device__ int  g_pos2   [N_EDGES];     // edge id -> in-CSR position
__device__ int  g_csr_out_dst[N_EDGES]; // out-CSR: dest node per out-edge

// ---------------- small utility kernels ------------------------------------
__global__ void k_hist(const int* __restrict__ ei, int* __restrict__ din, int* __restrict__ dout) {
    int e = blockIdx.x * 256 + threadIdx.x;
    if (e >= N_EDGES) return;
    atomicAdd(&dout[ei[e]], 1);            // src
    atomicAdd(&din[ei[N_EDGES + e]], 1);   // dst
}

// Phase A: per-block (512-elem) degree sums. grid = 2*SCAN_BLOCKS.
__global__ void k_blocksum(const int* __restrict__ din, const int* __restrict__ dout,
                           int* __restrict__ bsum) {
    const int* deg = (blockIdx.x < SCAN_BLOCKS) ? din : dout;
    const int b = (blockIdx.x < SCAN_BLOCKS) ? blockIdx.x : blockIdx.x - SCAN_BLOCKS;
    const int i = b * 512 + threadIdx.x;
    int v = (i < N_NODES) ? deg[i] : 0;

    __shared__ int ws[16];
    const int lane = threadIdx.x & 31, w = threadIdx.x >> 5;
#pragma unroll
    for (int o = 16; o; o >>= 1) v += __shfl_down_sync(0xffffffffu, v, o);
    if (lane == 0) ws[w] = v;
    __syncthreads();
    if (threadIdx.x < 16) {
        int t = ws[threadIdx.x];
#pragma unroll
        for (int o = 8; o; o >>= 1) t += __shfl_down_sync(0xffffu, t, o);
        if (threadIdx.x == 0) bsum[blockIdx.x] = t;
    }
}

// Phase B: exclusive scan of each 98-entry segment. grid = 2, block = 128.
__global__ void k_bscan(int* __restrict__ bsum, int* __restrict__ oin, int* __restrict__ oout) {
    __shared__ int sp[128];
    const int base = blockIdx.x * SCAN_BLOCKS;
    const int t = threadIdx.x;
    int v = (t < SCAN_BLOCKS) ? bsum[base + t] : 0;
    sp[t] = v;
    __syncthreads();
#pragma unroll
    for (int d = 1; d < 128; d <<= 1) {
        int u = (t >= d) ? sp[t - d] : 0;
        __syncthreads();
        sp[t] += u;
        __syncthreads();
    }
    if (t < SCAN_BLOCKS) bsum[base + t] = sp[t] - v;   // exclusive
    if (t == 0) (blockIdx.x ? oout : oin)[N_NODES] = N_EDGES;
}

// Phase C: per-block exclusive scan + block offset -> off/cur. grid = 2*SCAN_BLOCKS.
__global__ void k_scatteroff(const int* __restrict__ din, const int* __restrict__ dout,
                             const int* __restrict__ bsum,
                             int* __restrict__ oin, int* __restrict__ cin,
                             int* __restrict__ oout, int* __restrict__ cout_) {
    const bool isout = blockIdx.x >= SCAN_BLOCKS;
    const int* deg = isout ? dout : din;
    int* off = isout ? oout : oin;
    int* cur = isout ? cout_ : cin;
    const int b = isout ? blockIdx.x - SCAN_BLOCKS : blockIdx.x;
    const int i = b * 512 + threadIdx.x;
    int v = (i < N_NODES) ? deg[i] : 0;

    const int lane = threadIdx.x & 31, w = threadIdx.x >> 5;
    int incl = v;
#pragma unroll
    for (int o = 1; o < 32; o <<= 1) {
        int u = __shfl_up_sync(0xffffffffu, incl, o);
        if (lane >= o) incl += u;
    }
    __shared__ int ws[16], wo[16];
    if (lane == 31) ws[w] = incl;
    __syncthreads();
    if (threadIdx.x < 16) {
        int t = ws[threadIdx.x];
        int ti = t;
#pragma unroll
        for (int o = 1; o < 16; o <<= 1) {
            int u = __shfl_up_sync(0xffffu, ti, o);
            if (threadIdx.x >= o) ti += u;
        }
        wo[threadIdx.x] = ti - t;                      // exclusive warp offset
    }
    __syncthreads();
    int excl = incl - v + wo[w] + bsum[blockIdx.x];
    if (i < N_NODES) { off[i] = excl; cur[i] = excl; }
}

// Runs AFTER all readers of din/dout: also re-zeroes them for the next replay.
__global__ void k_scatteridx(const int* __restrict__ ei,
                             int* __restrict__ cin, int* __restrict__ cout_,
                             int* __restrict__ pos2, int* __restrict__ odst,
                             int* __restrict__ din, int* __restrict__ dout) {
    int e = blockIdx.x * 256 + threadIdx.x;
    if (e >= N_EDGES) return;
    if (e < N_NODES) { din[e] = 0; dout[e] = 0; }      // reset for next replay
    int s = ei[e];
    int d = ei[N_EDGES + e];
    int p1 = atomicAdd(&cin[d], 1);
    pos2[e] = p1;                          // eid -> csr position (sequential write)
    int p2 = atomicAdd(&cout_[s], 1);
    odst[p2] = d;
}

__global__ void k_f2h(const float* __restrict__ s, __half* __restrict__ d, int n) {
    int i = blockIdx.x * blockDim.x + threadIdx.x;
    if (i < n) d[i] = __float2half(s[i]);
}

// Wc = Wg @ Wo  (fp32 accumulate, round once to half)
__global__ void k_wc(const float* __restrict__ Wg, const float* __restrict__ Wo,
                     __half* __restrict__ Wch) {
    int i = blockIdx.x * blockDim.x + threadIdx.x;
    int r = i >> 7, c = i & 127;
    float s = 0.f;
#pragma unroll 8
    for (int k = 0; k < 128; k++) s += Wg[r * 128 + k] * Wo[k * 128 + c];
    Wch[i] = __float2half(s);
}

__global__ void k_bgwo(const float* __restrict__ bg, const float* __restrict__ Wo,
                       float* __restrict__ bgwo) {
    int c = threadIdx.x;
    float s = 0.f;
#pragma unroll 8
    for (int k = 0; k < 128; k++) s += bg[k] * Wo[k * 128 + c];
    bgwo[c] = s;
}

__device__ __forceinline__ float4 ldh4(const __half* p) {   // 4 halves via one 8B LDG
    uint2 u = *reinterpret_cast<const uint2*>(p);
    __half2 h0 = *reinterpret_cast<__half2*>(&u.x);
    __half2 h1 = *reinterpret_cast<__half2*>(&u.y);
    float2 f0 = __half22float2(h0);
    float2 f1 = __half22float2(h1);
    return make_float4(f0.x, f0.y, f1.x, f1.y);
}

// ---------------- unified [M,128]@[128,128] GEMM ----------------------------
template <bool A_FP32, bool HALF_OUT>
__global__ void k_mm(const void* __restrict__ Av, const __half* __restrict__ B,
                     const float* __restrict__ bias, void* __restrict__ C, int m_rows) {
    extern __shared__ char smem[];
    __half* sA = reinterpret_cast<__half*>(smem);            // 128 x 136 halves
    __half* sB = reinterpret_cast<__half*>(smem + 34816);    // 128 x 136 halves
    float*  sT = reinterpret_cast<float*>(smem);             // reused staging

    const int tid  = threadIdx.x;
    const int warp = tid >> 5;
    const int lane = tid & 31;
    const size_t r0 = (size_t)blockIdx.x * 128;

    if (A_FP32) {
        const float* A = (const float*)Av;
#pragma unroll
        for (int j = 0; j < 16; j++) {
            int idx = j * 256 + tid;
            int row = idx >> 5, c4 = idx & 31;
            float4 v = make_float4(0.f, 0.f, 0.f, 0.f);
            if ((int)(r0 + row) < m_rows)
                v = *reinterpret_cast<const float4*>(A + (r0 + row) * 128 + c4 * 4);
            *reinterpret_cast<__half2*>(sA + row * 136 + c4 * 4)     = __floats2half2_rn(v.x, v.y);
            *reinterpret_cast<__half2*>(sA + row * 136 + c4 * 4 + 2) = __floats2half2_rn(v.z, v.w);
        }
    } else {
        const __half* A = (const __half*)Av;
#pragma unroll
        for (int j = 0; j < 32; j++) {
            int idx = j * 256 + tid;
            int row = idx >> 6, c2 = idx & 63;
            __half2 v = __floats2half2_rn(0.f, 0.f);
            if ((int)(r0 + row) < m_rows)
                v = *reinterpret_cast<const __half2*>(A + (r0 + row) * 128 + c2 * 2);
            *reinterpret_cast<__half2*>(sA + row * 136 + c2 * 2) = v;
        }
    }
#pragma unroll
    for (int j = 0; j < 32; j++) {                   // stage B
        int idx = j * 256 + tid;
        int row = idx >> 6, c2 = idx & 63;
        *reinterpret_cast<__half2*>(sB + row * 136 + c2 * 2) =
            *reinterpret_cast<const __half2*>(B + row * 128 + c2 * 2);
    }
    __syncthreads();

    wmma::fragment<wmma::accumulator, 16, 16, 16, float> acc[8];
#pragma unroll
    for (int n = 0; n < 8; n++) wmma::fill_fragment(acc[n], 0.f);

#pragma unroll
    for (int k = 0; k < 8; k++) {
        wmma::fragment<wmma::matrix_a, 16, 16, 16, __half, wmma::row_major> a;
        wmma::load_matrix_sync(a, sA + warp * 16 * 136 + k * 16, 136);
#pragma unroll
        for (int n = 0; n < 8; n++) {
            wmma::fragment<wmma::matrix_b, 16, 16, 16, __half, wmma::row_major> b;
            wmma::load_matrix_sync(b, sB + (k * 16) * 136 + n * 16, 136);
            wmma::mma_sync(acc[n], a, b, acc[n]);
        }
    }
    __syncthreads();                                 // done with sA/sB

    float* my = sT + warp * 16 * 132;
#pragma unroll
    for (int n = 0; n < 8; n++)
        wmma::store_matrix_sync(my + n * 16, acc[n], 132, wmma::mem_row_major);
    __syncwarp();                                    // each warp reads its own rows

    float4 bv = make_float4(0.f, 0.f, 0.f, 0.f);
    if (bias) bv = *reinterpret_cast<const float4*>(bias + lane * 4);

    const size_t row0 = r0 + warp * 16;
#pragma unroll
    for (int r = 0; r < 16; r++) {
        float4 v = *reinterpret_cast<const float4*>(my + r * 132 + lane * 4);
        v.x += bv.x; v.y += bv.y; v.z += bv.z; v.w += bv.w;
        if (HALF_OUT) {
            __half2 h0 = __floats2half2_rn(v.x, v.y);
            __half2 h1 = __floats2half2_rn(v.z, v.w);
            uint2 u = make_uint2(*(unsigned*)&h0, *(unsigned*)&h1);
            *reinterpret_cast<uint2*>((__half*)C + (row0 + r) * 128 + lane * 4) = u;
        } else {
            *reinterpret_cast<float4*>((float*)C + (row0 + r) * 128 + lane * 4) = v;
        }
    }
}

// ------- edge GEMM + xs fold + CSR scatter-write ----------------------------
// eawh[pos2[e]] = half( ea[e]@We2 + xs[src[e]] )
__global__ void k_eaw(const float* __restrict__ ea, const int* __restrict__ ei,
                      const __half* __restrict__ xsh, const int* __restrict__ pos2,
                      const __half* __restrict__ W2, __half* __restrict__ eaw) {
    extern __shared__ char smem[];
    __half* sA   = reinterpret_cast<__half*>(smem);            // 128 x 136
    __half* sB   = reinterpret_cast<__half*>(smem + 34816);    // 128 x 136
    int*    sSrc = reinterpret_cast<int*>(smem + 69632);       // 128
    int*    sPos = reinterpret_cast<int*>(smem + 70144);       // 128
    float*  sT   = reinterpret_cast<float*>(smem);             // per-warp strips

    const int tid  = threadIdx.x;
    const int warp = tid >> 5;
    const int lane = tid & 31;
    const size_t e0 = (size_t)blockIdx.x * 128;

    if (tid < 128) {
        sSrc[tid] = ei[e0 + tid];                    // src = edge_index[0]
        sPos[tid] = pos2[e0 + tid];
    }
#pragma unroll
    for (int j = 0; j < 16; j++) {                   // stream A tile (sequential DRAM)
        int idx = j * 256 + tid;
        int row = idx >> 5, c4 = idx & 31;
        float4 v = *reinterpret_cast<const float4*>(ea + (e0 + row) * 128 + c4 * 4);
        *reinterpret_cast<__half2*>(sA + row * 136 + c4 * 4)     = __floats2half2_rn(v.x, v.y);
        *reinterpret_cast<__half2*>(sA + row * 136 + c4 * 4 + 2) = __floats2half2_rn(v.z, v.w);
    }
#pragma unroll
    for (int j = 0; j < 32; j++) {                   // stage W2 (L2-resident)
        int idx = j * 256 + tid;
        int row = idx >> 6, c2 = idx & 63;
        *reinterpret_cast<__half2*>(sB + row * 136 + c2 * 2) =
            *reinterpret_cast<const __half2*>(W2 + row * 128 + c2 * 2);
    }
    __syncthreads();

    // prefetch xs[src] for this warp's 16 rows — latency hides under the mma
    uint2 pre[16];
#pragma unroll
    for (int r = 0; r < 16; r++) {
        int src = sSrc[warp * 16 + r];
        pre[r] = *reinterpret_cast<const uint2*>(xsh + (size_t)src * 128 + lane * 4);
    }

    wmma::fragment<wmma::accumulator, 16, 16, 16, float> acc[8];
#pragma unroll
    for (int n = 0; n < 8; n++) wmma::fill_fragment(acc[n], 0.f);

#pragma unroll
    for (int k = 0; k < 8; k++) {
        wmma::fragment<wmma::matrix_a, 16, 16, 16, __half, wmma::row_major> a;
        wmma::load_matrix_sync(a, sA + warp * 16 * 136 + k * 16, 136);
#pragma unroll
        for (int n = 0; n < 8; n++) {
            wmma::fragment<wmma::matrix_b, 16, 16, 16, __half, wmma::row_major> b;
            wmma::load_matrix_sync(b, sB + (k * 16) * 136 + n * 16, 136);
            wmma::mma_sync(acc[n], a, b, acc[n]);
        }
    }
    __syncthreads();                                 // all warps done reading sA/sB

    // warp-local epilogue
    float* my = sT + warp * (16 * 132);
#pragma unroll
    for (int n = 0; n < 8; n++)
        wmma::store_matrix_sync(my + n * 16, acc[n], 132, wmma::mem_row_major);
    __syncwarp();

#pragma unroll
    for (int r = 0; r < 16; r++) {
        int row = warp * 16 + r;
        float4 t = *reinterpret_cast<const float4*>(my + r * 132 + lane * 4);
        __half2 p0 = *reinterpret_cast<__half2*>(&pre[r].x);
        __half2 p1 = *reinterpret_cast<__half2*>(&pre[r].y);
        float2 v0 = __half22float2(p0);
        float2 v1 = __half22float2(p1);
        __half2 h0 = __floats2half2_rn(t.x + v0.x, t.y + v0.y);
        __half2 h1 = __floats2half2_rn(t.z + v1.x, t.w + v1.y);
        uint2 u = make_uint2(*(unsigned*)&h0, *(unsigned*)&h1);
        *reinterpret_cast<uint2*>(eaw + (size_t)sPos[row] * 128 + lane * 4) = u;
    }
}

// ------- aggregation: aggh[n] = half( sum silu(xd[n] + eawh[i]) ), sequential
__device__ __forceinline__ float silu1(float v) { return v / (1.f + __expf(-v)); }

__global__ void k_agg(const int* __restrict__ off,
                      const float* __restrict__ xd, const __half* __restrict__ eaw,
                      __half* __restrict__ aggh) {
    const int w    = (blockIdx.x * 256 + threadIdx.x) >> 5;    // node id
    const int lane = threadIdx.x & 31;
    if (w >= N_NODES) return;

    float4 base = *reinterpret_cast<const float4*>(xd + (size_t)w * 128 + lane * 4);

    float4 acc = make_float4(0.f, 0.f, 0.f, 0.f);
    const int beg = off[w], end = off[w + 1];
#pragma unroll 4
    for (int i = beg; i < end; i++) {                // sequential eaw stream
        float4 t = ldh4(eaw + (size_t)i * 128 + lane * 4);
        acc.x += silu1(base.x + t.x);
        acc.y += silu1(base.y + t.y);
        acc.z += silu1(base.z + t.z);
        acc.w += silu1(base.w + t.w);
    }
    __half2 h0 = __floats2half2_rn(acc.x, acc.y);
    __half2 h1 = __floats2half2_rn(acc.z, acc.w);
    uint2 u = make_uint2(*(unsigned*)&h0, *(unsigned*)&h1);
    *reinterpret_cast<uint2*>(aggh + (size_t)w * 128 + lane * 4) = u;
}

// ---------------- output: out[n] = bo + sum_out hW[dst] ---------------------
__global__ void k_out(const int* __restrict__ off, const int* __restrict__ odst,
                      const __half* __restrict__ hWh, const float* __restrict__ bo,
                      float* __restrict__ out) {
    const int w    = (blockIdx.x * 256 + threadIdx.x) >> 5;
    const int lane = threadIdx.x & 31;
    if (w >= N_NODES) return;

    float4 acc = *reinterpret_cast<const float4*>(bo + lane * 4);
    const int beg = off[w], end = off[w + 1];
#pragma unroll 4
    for (int i = beg; i < end; i++) {
        int d = odst[i];
        float4 v = ldh4(hWh + (size_t)d * 128 + lane * 4);
        acc.x += v.x; acc.y += v.y; acc.z += v.z; acc.w += v.w;
    }
    *reinterpret_cast<float4*>(out + (size_t)w * 128 + lane * 4) = acc;
}

// ---------------- launch ----------------------------------------------------
extern "C" void kernel_launch(void* const* d_in, const int* in_sizes, int n_in,
                              void* d_out, int out_size) {
    const float* x  = (const float*)d_in[0];
    const int*   ei = (const int*)d_in[1];     // int32 (JAX x64 disabled)
    const float* ea = (const float*)d_in[2];
    const float* We = (const float*)d_in[3];
    const float* be = (const float*)d_in[4];
    const float* Wg = (const float*)d_in[5];
    const float* bg = (const float*)d_in[6];
    // d_in[7]=Wa, d_in[8]=ba: dead (softmax over size-1 axis == 1)
    const float* Wo = (const float*)d_in[9];
    const float* bo = (const float*)d_in[10];
    float*       out = (float*)d_out;

    void *p;
    __half *xsh, *aggh, *hWh, *eawh, *Weh, *Wch;
    float *xd, *bgwo;
    int *din, *dout_, *oin, *oout, *cin, *cout_, *bsum, *pos2, *odst;
    cudaGetSymbolAddress(&p, g_xd);          xd    = (float*)p;
    cudaGetSymbolAddress(&p, g_xsh);         xsh   = (__half*)p;
    cudaGetSymbolAddress(&p, g_aggh);        aggh  = (__half*)p;
    cudaGetSymbolAddress(&p, g_hWh);         hWh   = (__half*)p;
    cudaGetSymbolAddress(&p, g_eawh);        eawh  = (__half*)p;
    cudaGetSymbolAddress(&p, g_Weh);         Weh   = (__half*)p;
    cudaGetSymbolAddress(&p, g_Wch);         Wch   = (__half*)p;
    cudaGetSymbolAddress(&p, g_bgwo);        bgwo  = (float*)p;
    cudaGetSymbolAddress(&p, g_deg_in);      din   = (int*)p;
    cudaGetSymbolAddress(&p, g_deg_out);     dout_ = (int*)p;
    cudaGetSymbolAddress(&p, g_off_in);      oin   = (int*)p;
    cudaGetSymbolAddress(&p, g_off_out);     oout  = (int*)p;
    cudaGetSymbolAddress(&p, g_cur_in);      cin   = (int*)p;
    cudaGetSymbolAddress(&p, g_cur_out);     cout_ = (int*)p;
    cudaGetSymbolAddress(&p, g_bsum);        bsum  = (int*)p;
    cudaGetSymbolAddress(&p, g_pos2);        pos2  = (int*)p;
    cudaGetSymbolAddress(&p, g_csr_out_dst); odst  = (int*)p;

    const size_t mm_shmem  = 69632;           // sA + sB
    const size_t eaw_shmem = 70656;           // sA + sB + sSrc + sPos
    cudaFuncSetAttribute(k_mm<true,  false>, cudaFuncAttributeMaxDynamicSharedMemorySize, (int)mm_shmem);
    cudaFuncSetAttribute(k_mm<true,  true >, cudaFuncAttributeMaxDynamicSharedMemorySize, (int)mm_shmem);
    cudaFuncSetAttribute(k_mm<false, true >, cudaFuncAttributeMaxDynamicSharedMemorySize, (int)mm_shmem);
    cudaFuncSetAttribute(k_eaw,              cudaFuncAttributeMaxDynamicSharedMemorySize, (int)eaw_shmem);

    const int gblocks = NPAD / 128;           // 391
    const int eblocks = N_EDGES / 128;        // 6250
    const int nwarp_blocks = (N_NODES * 32 + 255) / 256;   // 6250

    // deg arrays enter zeroed (static init on first call; k_scatteridx re-zeroes
    // them each run for the next replay)
    k_f2h<<<(3 * WSZ + 255) / 256, 256>>>(We, Weh, 3 * WSZ);
    k_hist<<<(N_EDGES + 255) / 256, 256>>>(ei, din, dout_);
    k_mm<true, true ><<<gblocks, 256, mm_shmem>>>(x, Weh + WSZ, nullptr, xsh, N_NODES);

    // hierarchical CSR offset scan
    k_blocksum<<<2 * SCAN_BLOCKS, 512>>>(din, dout_, bsum);
    k_bscan<<<2, 128>>>(bsum, oin, oout);
    k_scatteroff<<<2 * SCAN_BLOCKS, 512>>>(din, dout_, bsum, oin, cin, oout, cout_);

    k_scatteridx<<<(N_EDGES + 255) / 256, 256>>>(ei, cin, cout_, pos2, odst, din, dout_);

    // edge GEMM + xs fold, scatter-written into in-CSR order
    k_eaw<<<eblocks, 256, eaw_shmem>>>(ea, ei, xsh, pos2, Weh + 2 * WSZ, eawh);

    k_wc<<<64, 256>>>(Wg, Wo, Wch);
    k_bgwo<<<1, 128>>>(bg, Wo, bgwo);
    k_mm<true, false><<<gblocks, 256, mm_shmem>>>(x, Weh, be, xd, N_NODES);   // be folded

    // fully sequential aggregation
    k_agg<<<nwarp_blocks, 256>>>(oin, xd, eawh, aggh);

    // hW = agg @ (Wg@Wo) + bg@Wo
    k_mm<false, true><<<gblocks, 256, mm_shmem>>>(aggh, Wch, bgwo, hWh, NPAD);

    // out[n] = bo + sum hW[dst] over out-edges
    k_out<<<nwarp_blocks, 256>>>(oout, odst, hWh, bo, out);
}